// round 6
// baseline (speedup 1.0000x reference)
#include <cuda_runtime.h>
#include <cstdint>

// out[n, d] = x[n, d] * w[d];  N = DIM = 8192, fp32.
// R6: 256-bit LDG/STG variant (Blackwell ld/st.global.v8.f32).
// Each thread owns one 32-byte column group (8 floats); weight in registers.
// Halves request count vs the 128-bit kernels pinned at 6.33 TB/s.

static constexpr int DIM   = 8192;
static constexpr int DIM8  = DIM / 8;              // 1024 8-float groups per row
static constexpr int THREADS = 256;
static constexpr int COLBLOCKS = DIM8 / THREADS;   // 4 column-blocks per row
static constexpr int ROWGROUPS = 256;
static constexpr int UNROLL = 4;

struct f8 { float v[8]; };

__device__ __forceinline__ f8 ldg256(const float* p)
{
    f8 r;
    asm volatile("ld.global.nc.v8.f32 {%0,%1,%2,%3,%4,%5,%6,%7}, [%8];"
                 : "=f"(r.v[0]), "=f"(r.v[1]), "=f"(r.v[2]), "=f"(r.v[3]),
                   "=f"(r.v[4]), "=f"(r.v[5]), "=f"(r.v[6]), "=f"(r.v[7])
                 : "l"(p));
    return r;
}

__device__ __forceinline__ void stg256(float* p, const f8& r)
{
    asm volatile("st.global.v8.f32 [%0], {%1,%2,%3,%4,%5,%6,%7,%8};"
                 :: "l"(p),
                    "f"(r.v[0]), "f"(r.v[1]), "f"(r.v[2]), "f"(r.v[3]),
                    "f"(r.v[4]), "f"(r.v[5]), "f"(r.v[6]), "f"(r.v[7])
                 : "memory");
}

__global__ void __launch_bounds__(THREADS)
diag_scale_v8_kernel(const float* __restrict__ x,
                     const float* __restrict__ w,
                     float* __restrict__ out,
                     int n_rows)
{
    const int cb = blockIdx.x & (COLBLOCKS - 1);       // 0..3
    const int rg = blockIdx.x >> 2;                    // 0..ROWGROUPS-1
    const int col8 = cb * THREADS + threadIdx.x;       // fixed 8-float group
    const int colf = col8 * 8;                         // float offset in row

    // weight for this thread's 8 columns, loaded once
    f8 wv;
    #pragma unroll
    for (int j = 0; j < 8; ++j) wv.v[j] = __ldg(&w[colf + j]);

    const long long rstride = (long long)ROWGROUPS * DIM;    // floats between rows
    const float* xp = x   + (long long)rg * DIM + colf;
    float*       op = out + (long long)rg * DIM + colf;

    const int iters = n_rows / (ROWGROUPS * UNROLL);          // 8 for N=8192

    for (int it = 0; it < iters; ++it) {
        f8 v[UNROLL];
        #pragma unroll
        for (int u = 0; u < UNROLL; ++u)
            v[u] = ldg256(xp + (long long)u * rstride);       // 4x LDG.256 in flight
        #pragma unroll
        for (int u = 0; u < UNROLL; ++u) {
            #pragma unroll
            for (int j = 0; j < 8; ++j) v[u].v[j] *= wv.v[j];
            stg256(op + (long long)u * rstride, v[u]);        // STG.256
        }
        xp += (long long)UNROLL * rstride;
        op += (long long)UNROLL * rstride;
    }
}

// Generic fallback (correct for any shape).
__global__ void __launch_bounds__(256)
diag_scale_fallback(const float4* __restrict__ x,
                    const float4* __restrict__ w4,
                    float4* __restrict__ out,
                    long long n4, int dim4)
{
    long long i = (long long)blockIdx.x * blockDim.x + threadIdx.x;
    long long stride = (long long)gridDim.x * blockDim.x;
    for (; i < n4; i += stride) {
        float4 v = x[i];
        int col4 = (int)(i % dim4);
        float4 wv = __ldg(&w4[col4]);
        v.x *= wv.x; v.y *= wv.y; v.z *= wv.z; v.w *= wv.w;
        out[i] = v;
    }
}

extern "C" void kernel_launch(void* const* d_in, const int* in_sizes, int n_in,
                              void* d_out, int out_size)
{
    long long n_elems = (long long)out_size;
    int dim = in_sizes[1];
    int n_rows = (int)(n_elems / dim);

    bool fast_ok = (dim == DIM) && (n_rows % (ROWGROUPS * UNROLL) == 0);

    if (fast_ok) {
        const float* x = (const float*)d_in[0];
        const float* w = (const float*)d_in[1];
        float* out = (float*)d_out;
        int blocks = COLBLOCKS * ROWGROUPS;    // 1024 blocks
        diag_scale_v8_kernel<<<blocks, THREADS>>>(x, w, out, n_rows);
    } else {
        const float4* x  = (const float4*)d_in[0];
        const float4* w4 = (const float4*)d_in[1];
        float4* out = (float4*)d_out;
        long long n4 = n_elems / 4;
        const int threads = 256;
        int blocks = 148 * 8 * 4;
        long long needed = (n4 + threads - 1) / threads;
        if ((long long)blocks > needed) blocks = (int)needed;
        diag_scale_fallback<<<blocks, threads>>>(x, w4, out, n4, dim / 4);
    }
}

// round 7
// speedup vs baseline: 1.0807x; 1.0807x over previous
#include <cuda_runtime.h>
#include <cstdint>

// out[n, d] = x[n, d] * w[d];  N = DIM = 8192, fp32.
// FINAL (verified twice at 84.0us bench / 76.7us kernel / 6.33 TB/s).
// Ceiling analysis R1-R6: six structurally different kernels (grid-stride,
// column-owning MLP4/MLP8, cache-policy hints, sw-pipeline, 256-bit v8) pin
// at or below 6.33 TB/s -> mixed 50/50 R/W HBM3e stream limit (~79% of spec).
// Each thread owns one float4-column; weight in registers; 8 front-batched
// LDG.128 then 8 STG.128 per iteration; evict-first policy both directions.

static constexpr int DIM   = 8192;
static constexpr int DIM4  = DIM / 4;              // 2048 float4 columns
static constexpr int THREADS = 256;
static constexpr int COLBLOCKS = DIM4 / THREADS;   // 8 column-blocks per row
static constexpr int ROWGROUPS = 256;
static constexpr int UNROLL = 8;

__global__ void __launch_bounds__(THREADS)
diag_scale_stream_kernel(const float4* __restrict__ x,
                         const float4* __restrict__ w4,
                         float4* __restrict__ out,
                         int n_rows)
{
    const int cb = blockIdx.x & (COLBLOCKS - 1);
    const int rg = blockIdx.x >> 3;
    const int col4 = cb * THREADS + threadIdx.x;

    const float4 wv = __ldg(&w4[col4]);            // once; stays in registers

    const long long rstride = (long long)ROWGROUPS * DIM4;   // elems between rows
    const float4* xp = x   + (long long)rg * DIM4 + col4;
    float4*       op = out + (long long)rg * DIM4 + col4;

    const int iters = n_rows / (ROWGROUPS * UNROLL);          // 4 for N=8192

    for (int it = 0; it < iters; ++it) {
        float4 v[UNROLL];
        #pragma unroll
        for (int u = 0; u < UNROLL; ++u)
            v[u] = __ldcs(xp + (long long)u * rstride);       // 8 reads in flight
        #pragma unroll
        for (int u = 0; u < UNROLL; ++u) {
            v[u].x *= wv.x;
            v[u].y *= wv.y;
            v[u].z *= wv.z;
            v[u].w *= wv.w;
            __stcs(op + (long long)u * rstride, v[u]);        // 8 writes
        }
        xp += (long long)UNROLL * rstride;
        op += (long long)UNROLL * rstride;
    }
}

// Generic fallback (correct for any shape).
__global__ void __launch_bounds__(256)
diag_scale_fallback(const float4* __restrict__ x,
                    const float4* __restrict__ w4,
                    float4* __restrict__ out,
                    long long n4, int dim4)
{
    long long i = (long long)blockIdx.x * blockDim.x + threadIdx.x;
    long long stride = (long long)gridDim.x * blockDim.x;
    for (; i < n4; i += stride) {
        float4 v = x[i];
        int col4 = (int)(i % dim4);
        float4 wv = __ldg(&w4[col4]);
        v.x *= wv.x; v.y *= wv.y; v.z *= wv.z; v.w *= wv.w;
        out[i] = v;
    }
}

extern "C" void kernel_launch(void* const* d_in, const int* in_sizes, int n_in,
                              void* d_out, int out_size)
{
    const float4* x  = (const float4*)d_in[0];
    const float4* w4 = (const float4*)d_in[1];
    float4* out = (float4*)d_out;

    long long n_elems = (long long)out_size;
    int dim = in_sizes[1];
    int n_rows = (int)(n_elems / dim);

    bool fast_ok = (dim == DIM) && (n_rows % (ROWGROUPS * UNROLL) == 0);

    if (fast_ok) {
        int blocks = COLBLOCKS * ROWGROUPS;    // 2048 blocks
        diag_scale_stream_kernel<<<blocks, THREADS>>>(x, w4, out, n_rows);
    } else {
        long long n4 = n_elems / 4;
        const int threads = 256;
        int blocks = 148 * 8 * 4;
        long long needed = (n4 + threads - 1) / threads;
        if ((long long)blocks > needed) blocks = (int)needed;
        diag_scale_fallback<<<blocks, threads>>>(x, w4, out, n4, dim / 4);
    }
}